// round 8
// baseline (speedup 1.0000x reference)
#include <cuda_runtime.h>
#include <cstdint>
#include <math.h>

#define BB 64
#define PP 16320
#define OO 24
#define CC 81
#define CROWS 32              // rows per chunk in k_main
#define CF4   (CROWS*CC/4)    // 648 float4 per chunk
#define NCHUNK 30             // chunks per block; 17*30*32 = 16320 = PP

// ---------------- device scratch (self-resetting across replays) ----------------
__device__ double g_loss_l;                          // reset by k_final
__device__ double g_loss_c;                          // reset by k_final
__device__ int    g_pos_count[BB];                   // reset by k_final
__device__ unsigned long long g_best_prior[BB * OO]; // re-armed by k_topk
__device__ unsigned char g_match[(size_t)BB * PP];   // fully overwritten each run
__device__ float  g_ce_mine[(size_t)BB * PP];        // fully overwritten each run

__device__ __forceinline__ void cp16(void* smem, const void* gmem) {
    unsigned sa = (unsigned)__cvta_generic_to_shared(smem);
    asm volatile("cp.async.cg.shared.global [%0], [%1], 16;\n" :: "r"(sa), "l"(gmem));
}

// ---------------- kernel 1: matching (division-free fraction compares) ----------------
// grid: (128, 64), block 128 (4 warps)
__global__ void __launch_bounds__(128)
k_match(const float* __restrict__ arm_loc,
        const float* __restrict__ priors,
        const float* __restrict__ gt_boxes) {
    int b = blockIdx.y;
    int tid = threadIdx.x;
    int w = tid >> 5, lane = tid & 31;
    int p = blockIdx.x * 128 + tid;

    __shared__ float4 s_gt[OO];
    __shared__ float  s_at[OO];
    __shared__ float  s_I[4][32][25];   // pad 25 -> conflict-free
    __shared__ float  s_D[4][32][25];
    if (tid < OO) {
        float4 t = ((const float4*)gt_boxes)[b * OO + tid];
        s_gt[tid] = t;
        s_at[tid] = (t.z - t.x) * (t.w - t.y);
    }
    __syncthreads();

    bool valid = (p < PP);
    float dx1 = 0.f, dy1 = 0.f, dx2 = 0.f, dy2 = 0.f, area_d = 0.f;
    if (valid) {
        float4 pr = ((const float4*)priors)[p];
        float4 lc = ((const float4*)arm_loc)[(size_t)b * PP + p];
        float cx = pr.x + lc.x * 0.1f * pr.z;
        float cy = pr.y + lc.y * 0.1f * pr.w;
        float wd = pr.z * __expf(lc.z * 0.2f);
        float ht = pr.w * __expf(lc.w * 0.2f);
        dx1 = cx - wd * 0.5f; dy1 = cy - ht * 0.5f;
        dx2 = cx + wd * 0.5f; dy2 = cy + ht * 0.5f;
        area_d = (dx2 - dx1) * (dy2 - dy1);
    }

    float bI = 0.f, bD = 1.f; int besto = 0;
    #pragma unroll 6
    for (int o = 0; o < OO; o++) {
        float I = 0.f, D = 1.f;
        if (valid) {
            float4 t = s_gt[o];
            float lx = fmaxf(t.x, dx1), ly = fmaxf(t.y, dy1);
            float rx = fminf(t.z, dx2), ry = fminf(t.w, dy2);
            float iw = fmaxf(rx - lx, 0.f), ih = fmaxf(ry - ly, 0.f);
            I = iw * ih;
            D = s_at[o] + area_d - I;
            if (I * bD > bI * D) { bI = I; bD = D; besto = o; }
        }
        s_I[w][lane][o] = I;
        s_D[w][lane][o] = D;
    }
    __syncwarp();

    if (lane < OO) {
        float wI = s_I[w][0][lane], wD = s_D[w][0][lane]; int wj = 0;
        #pragma unroll 8
        for (int j = 1; j < 32; j++) {
            float I = s_I[w][j][lane], D = s_D[w][j][lane];
            if (I * wD > wI * D) { wI = I; wD = D; wj = j; }
        }
        if (wI > 0.f) {
            float iou = wI / wD;
            unsigned pw = (unsigned)(blockIdx.x * 128 + w * 32 + wj);
            unsigned long long cand =
                (((unsigned long long)__float_as_uint(iou)) << 32) |
                (unsigned long long)(0xFFFFFFFFu - pw);
            atomicMax(&g_best_prior[b * OO + lane], cand);
        }
    }

    if (valid) {
        unsigned char fl = (2.f * bI >= bD) ? 0x80 : 0;   // iou >= 0.5
        g_match[(size_t)b * PP + p] = (unsigned char)besto | fl;
    }
}

// ---------------- kernel 2: fused CE / positive losses — cp.async pipelined ----------------
// grid: (17, 64), block 256, 8 blocks/SM; each block streams 30 chunks of 32 rows
__global__ void __launch_bounds__(256, 8)
k_main(const float* __restrict__ arm_loc,
       const float* __restrict__ arm_conf,
       const float* __restrict__ odm_loc,
       const float* __restrict__ odm_conf,
       const float* __restrict__ priors,
       const float* __restrict__ gt_boxes,
       const int*   __restrict__ gt_labels) {
    __shared__ float  s_buf[2][CROWS * CC];  // 2 x 10368 B
    __shared__ float4 s_gtb[OO];
    __shared__ int    s_lab[OO];
    __shared__ int    s_fp[OO];              // forced prior index per object

    int b = blockIdx.y;
    int tid = threadIdx.x;
    int chunk0 = blockIdx.x * NCHUNK;        // within-batch chunk index

    if (tid < OO) {
        unsigned long long fc = g_best_prior[b * OO + tid];
        // hi==0 (incl. first-call zero-init) -> reference forces prior 0
        s_fp[tid] = (fc >> 32) ? (int)(0xFFFFFFFFu - (unsigned)(fc & 0xFFFFFFFFu)) : 0;
        s_gtb[tid] = ((const float4*)gt_boxes)[b * OO + tid];
        s_lab[tid] = gt_labels[b * OO + tid];
    }

    const float4* cbase = (const float4*)odm_conf;   // (b*PP+p0)*CC divisible by 4

    // prologue: issue chunk 0
    {
        const float4* src = cbase + ((size_t)b * PP + (size_t)chunk0 * CROWS) * CC / 4;
        for (int i = tid; i < CF4; i += 256)
            cp16(&s_buf[0][i * 4], src + i);
        asm volatile("cp.async.commit_group;\n" ::);
    }

    int r = tid >> 3, q = tid & 7;           // 32 rows, 8 lanes per row

    for (int c = 0; c < NCHUNK; c++) {
        int cur = c & 1;
        if (c + 1 < NCHUNK) {
            const float4* src = cbase +
                ((size_t)b * PP + (size_t)(chunk0 + c + 1) * CROWS) * CC / 4;
            float* dstb = s_buf[cur ^ 1];
            for (int i = tid; i < CF4; i += 256)
                cp16(&dstb[i * 4], src + i);
            asm volatile("cp.async.commit_group;\n" ::);
            asm volatile("cp.async.wait_group 1;\n" ::);
        } else {
            asm volatile("cp.async.wait_group 0;\n" ::);
        }
        __syncthreads();

        int p0 = (chunk0 + c) * CROWS;
        size_t rowbase = (size_t)b * PP + p0;
        const float* rp = s_buf[cur] + r * CC;

        // lane q sums elements [q*10, q*10+10); q==0 also adds element 80
        int base = q * 10;
        float a0 = 0.f, a1 = 0.f;
        #pragma unroll
        for (int j = 0; j < 10; j += 2) {
            a0 += __expf(rp[base + j]);
            a1 += __expf(rp[base + j + 1]);
        }
        float e = a0 + a1;
        if (q == 0) e += __expf(rp[80]);
        e += __shfl_xor_sync(0xFFFFFFFFu, e, 1);
        e += __shfl_xor_sync(0xFFFFFFFFu, e, 2);
        e += __shfl_xor_sync(0xFFFFFFFFu, e, 4);

        // forced-positive detection, 3 objects per lane, max-o wins (ref last-write)
        int p_row = p0 + r;
        int fo = -1;
        #pragma unroll
        for (int j = 0; j < 3; j++) {
            int o = q * 3 + j;
            if (s_fp[o] == p_row) fo = o;     // ascending j: larger o overwrites
        }
        fo = max(fo, __shfl_xor_sync(0xFFFFFFFFu, fo, 1));
        fo = max(fo, __shfl_xor_sync(0xFFFFFFFFu, fo, 2));
        fo = max(fo, __shfl_xor_sync(0xFFFFFFFFu, fo, 4));

        if (q == 0) {                        // row leader epilogue
            float lse = __logf(e);
            size_t idx = rowbase + r;
            unsigned char m = g_match[idx];
            int obj; bool flag;
            if (fo >= 0) { obj = fo; flag = true; }
            else         { obj = m & 0x1F; flag = (m & 0x80) != 0; }
            int conf_t = flag ? s_lab[obj] : 0;
            float ce = lse - rp[conf_t];

            float2 ac = ((const float2*)arm_conf)[idx];
            // softmax[1] > 0.01  <=>  (y - x) > log(0.01/0.99)
            bool pos = (conf_t > 0) && ((ac.y - ac.x) > -4.5951199f);

            g_ce_mine[idx] = pos ? 0.f : ce;

            if (pos) {                        // rare (~24/batch)
                float4 pr = ((const float4*)priors)[p_row];
                float4 al = ((const float4*)arm_loc)[idx];
                float cx = pr.x + al.x * 0.1f * pr.z;
                float cy = pr.y + al.y * 0.1f * pr.w;
                float wd = pr.z * __expf(al.z * 0.2f);
                float ht = pr.w * __expf(al.w * 0.2f);
                float x1 = cx - wd * 0.5f, y1 = cy - ht * 0.5f;
                float x2 = cx + wd * 0.5f, y2 = cy + ht * 0.5f;
                float dcx = (x1 + x2) * 0.5f, dcy = (y1 + y2) * 0.5f;
                float dw = x2 - x1, dh = y2 - y1;
                float4 t = s_gtb[obj];
                float gcx = ((t.x + t.z) * 0.5f - dcx) / (0.1f * dw);
                float gcy = ((t.y + t.w) * 0.5f - dcy) / (0.1f * dh);
                float gw  = __logf((t.z - t.x) / dw) / 0.2f;
                float gh  = __logf((t.w - t.y) / dh) / 0.2f;
                float4 ol = ((const float4*)odm_loc)[idx];
                float d0 = fabsf(ol.x - gcx), d1 = fabsf(ol.y - gcy);
                float d2 = fabsf(ol.z - gw),  d3 = fabsf(ol.w - gh);
                float sl = (d0 < 1.f ? 0.5f * d0 * d0 : d0 - 0.5f)
                         + (d1 < 1.f ? 0.5f * d1 * d1 : d1 - 0.5f)
                         + (d2 < 1.f ? 0.5f * d2 * d2 : d2 - 0.5f)
                         + (d3 < 1.f ? 0.5f * d3 * d3 : d3 - 0.5f);
                atomicAdd(&g_loss_l, (double)sl);
                atomicAdd(&g_loss_c, (double)ce);
                atomicAdd(&g_pos_count[b], 1);
            }
        }
        __syncthreads();   // everyone done with s_buf[cur] before it is refilled
    }
}

// ---------------- kernel 3: per-batch top-k sum, 4-pass radix select ----------------
// grid: 64 blocks, block 1024, dynamic smem = PP*4. Also re-arms g_best_prior.
__global__ void __launch_bounds__(1024) k_topk() {
    int b = blockIdx.x;
    extern __shared__ unsigned sm[];
    __shared__ int s_hist[256];
    __shared__ int s_rem;
    __shared__ unsigned s_pref;
    __shared__ double s_sum;
    __shared__ int s_cgt;
    int t = threadIdx.x;
    int lane = t & 31;

    if (t < OO) g_best_prior[b * OO + t] = 0x00000000FFFFFFFFull;  // next replay

    for (int i = t; i < PP; i += 1024)
        sm[i] = __float_as_uint(g_ce_mine[(size_t)b * PP + i]);
    if (t == 0) { s_sum = 0.0; s_cgt = 0; }
    __syncthreads();

    int np = g_pos_count[b];
    int k = 3 * np; if (k > PP - 1) k = PP - 1;
    if (k <= 0) return;

    int rem = k;
    unsigned pref = 0;
    #pragma unroll
    for (int d = 24; d >= 0; d -= 8) {
        if (t < 256) s_hist[t] = 0;
        __syncthreads();
        unsigned pmask = (d == 24) ? 0u : (0xFFFFFFFFu << (d + 8));
        for (int i = t; i < 16384; i += 1024) {   // uniform trips; collectives converged
            bool part = false; unsigned bin = 0;
            if (i < PP) {
                unsigned v = sm[i];
                part = ((v & pmask) == pref);
                bin = (v >> d) & 0xFFu;
            }
            unsigned act = __ballot_sync(0xFFFFFFFFu, part);
            if (part) {
                unsigned same = __match_any_sync(act, bin);
                if ((__ffs(same) - 1) == lane)
                    atomicAdd(&s_hist[bin], __popc(same));
            }
        }
        __syncthreads();
        if (t < 32) {
            int loc[8]; int s8 = 0;
            #pragma unroll
            for (int j = 0; j < 8; j++) { loc[j] = s_hist[t * 8 + j]; s8 += loc[j]; }
            int suf = s8;
            #pragma unroll
            for (int sh = 1; sh < 32; sh <<= 1) {
                int o = __shfl_down_sync(0xFFFFFFFFu, suf, sh);
                if (t + sh < 32) suf += o;
            }
            int above = suf - s8;
            int cand = -1, candgt = 0;
            int run = above;
            #pragma unroll
            for (int j = 7; j >= 0; j--) {
                int gt = run;
                run += loc[j];
                if (cand < 0 && run >= rem) { cand = t * 8 + j; candgt = gt; }
            }
            int wm = __reduce_max_sync(0xFFFFFFFFu, (unsigned)(cand + 1)) - 1;
            if (cand == wm && cand >= 0) {
                s_rem = rem - candgt;
                s_pref = pref | ((unsigned)cand << d);
            }
        }
        __syncthreads();
        rem = s_rem;
        pref = s_pref;
        __syncthreads();
    }
    unsigned lo = pref;

    double sum = 0.0; int cgt = 0;
    for (int i = t; i < PP; i += 1024) {
        unsigned v = sm[i];
        if (v > lo) { sum += (double)__uint_as_float(v); cgt++; }
    }
    #pragma unroll
    for (int s = 16; s > 0; s >>= 1) {
        sum += __shfl_xor_sync(0xFFFFFFFFu, sum, s);
        cgt += __shfl_xor_sync(0xFFFFFFFFu, cgt, s);
    }
    if (lane == 0) { atomicAdd(&s_sum, sum); atomicAdd(&s_cgt, cgt); }
    __syncthreads();
    if (t == 0) {
        double S = s_sum + (double)(k - s_cgt) * (double)__uint_as_float(lo);
        atomicAdd(&g_loss_c, S);
    }
}

// ---------------- kernel 4: finalize + reset accumulators ----------------
__global__ void k_final(float* __restrict__ out) {
    __shared__ int s[64];
    int t = threadIdx.x;
    s[t] = g_pos_count[t];
    g_pos_count[t] = 0;                       // reset for next replay
    __syncthreads();
    #pragma unroll
    for (int sft = 32; sft > 0; sft >>= 1) {
        if (t < sft) s[t] += s[t + sft];
        __syncthreads();
    }
    if (t == 0) {
        double N = (double)s[0];
        out[0] = (float)(g_loss_l / N);
        out[1] = (float)(g_loss_c / N);
        g_loss_l = 0.0;                       // reset for next replay
        g_loss_c = 0.0;
    }
}

// ---------------- launch ----------------
extern "C" void kernel_launch(void* const* d_in, const int* in_sizes, int n_in,
                              void* d_out, int out_size) {
    const float* arm_loc  = (const float*)d_in[0];
    const float* arm_conf = (const float*)d_in[1];
    const float* odm_loc  = (const float*)d_in[2];
    const float* odm_conf = (const float*)d_in[3];
    const float* priors   = (const float*)d_in[4];
    const float* gt_boxes = (const float*)d_in[5];
    const int*   gt_labels= (const int*)  d_in[6];
    float* out = (float*)d_out;

    cudaFuncSetAttribute(k_topk, cudaFuncAttributeMaxDynamicSharedMemorySize,
                         PP * (int)sizeof(unsigned));

    {
        dim3 g(128, BB);
        k_match<<<g, 128>>>(arm_loc, priors, gt_boxes);
    }
    {
        dim3 g(17, BB);
        k_main<<<g, 256>>>(arm_loc, arm_conf, odm_loc, odm_conf,
                           priors, gt_boxes, gt_labels);
    }
    k_topk<<<BB, 1024, PP * (int)sizeof(unsigned)>>>();
    k_final<<<1, 64>>>(out);
}

// round 9
// speedup vs baseline: 1.0886x; 1.0886x over previous
#include <cuda_runtime.h>
#include <cstdint>
#include <math.h>

#define BB 64
#define PP 16320
#define OO 24
#define CC 81
#define WCH 8                 // rows per chunk (per-warp)
#define WNC 5                 // chunks per warp -> 40 rows/warp
#define CHF (WCH*CC)          // 648 floats per chunk
#define CHF4 (CHF/4)          // 162 float4 per chunk

// ---------------- device scratch (self-resetting across replays) ----------------
__device__ double g_loss_l;                          // reset by k_final
__device__ double g_loss_c;                          // reset by k_final
__device__ int    g_pos_count[BB];                   // reset by k_final
__device__ unsigned long long g_best_prior[BB * OO]; // re-armed by k_topk
__device__ unsigned char g_match[(size_t)BB * PP];   // fully overwritten each run
__device__ float  g_ce_mine[(size_t)BB * PP];        // fully overwritten each run

__device__ __forceinline__ void cp16(void* smem, const void* gmem) {
    unsigned sa = (unsigned)__cvta_generic_to_shared(smem);
    asm volatile("cp.async.cg.shared.global [%0], [%1], 16;\n" :: "r"(sa), "l"(gmem));
}

// ---------------- kernel 1: matching (division-free fraction compares) ----------------
// grid: (128, 64), block 128 (4 warps)
__global__ void __launch_bounds__(128)
k_match(const float* __restrict__ arm_loc,
        const float* __restrict__ priors,
        const float* __restrict__ gt_boxes) {
    int b = blockIdx.y;
    int tid = threadIdx.x;
    int w = tid >> 5, lane = tid & 31;
    int p = blockIdx.x * 128 + tid;

    __shared__ float4 s_gt[OO];
    __shared__ float  s_at[OO];
    __shared__ float  s_I[4][32][25];   // pad 25 -> conflict-free
    __shared__ float  s_D[4][32][25];
    if (tid < OO) {
        float4 t = ((const float4*)gt_boxes)[b * OO + tid];
        s_gt[tid] = t;
        s_at[tid] = (t.z - t.x) * (t.w - t.y);
    }
    __syncthreads();

    bool valid = (p < PP);
    float dx1 = 0.f, dy1 = 0.f, dx2 = 0.f, dy2 = 0.f, area_d = 0.f;
    if (valid) {
        float4 pr = ((const float4*)priors)[p];
        float4 lc = ((const float4*)arm_loc)[(size_t)b * PP + p];
        float cx = pr.x + lc.x * 0.1f * pr.z;
        float cy = pr.y + lc.y * 0.1f * pr.w;
        float wd = pr.z * __expf(lc.z * 0.2f);
        float ht = pr.w * __expf(lc.w * 0.2f);
        dx1 = cx - wd * 0.5f; dy1 = cy - ht * 0.5f;
        dx2 = cx + wd * 0.5f; dy2 = cy + ht * 0.5f;
        area_d = (dx2 - dx1) * (dy2 - dy1);
    }

    float bI = 0.f, bD = 1.f; int besto = 0;
    #pragma unroll 6
    for (int o = 0; o < OO; o++) {
        float I = 0.f, D = 1.f;
        if (valid) {
            float4 t = s_gt[o];
            float lx = fmaxf(t.x, dx1), ly = fmaxf(t.y, dy1);
            float rx = fminf(t.z, dx2), ry = fminf(t.w, dy2);
            float iw = fmaxf(rx - lx, 0.f), ih = fmaxf(ry - ly, 0.f);
            I = iw * ih;
            D = s_at[o] + area_d - I;
            if (I * bD > bI * D) { bI = I; bD = D; besto = o; }
        }
        s_I[w][lane][o] = I;
        s_D[w][lane][o] = D;
    }
    __syncwarp();

    if (lane < OO) {
        float wI = s_I[w][0][lane], wD = s_D[w][0][lane]; int wj = 0;
        #pragma unroll 8
        for (int j = 1; j < 32; j++) {
            float I = s_I[w][j][lane], D = s_D[w][j][lane];
            if (I * wD > wI * D) { wI = I; wD = D; wj = j; }
        }
        if (wI > 0.f) {
            float iou = wI / wD;
            unsigned pw = (unsigned)(blockIdx.x * 128 + w * 32 + wj);
            unsigned long long cand =
                (((unsigned long long)__float_as_uint(iou)) << 32) |
                (unsigned long long)(0xFFFFFFFFu - pw);
            atomicMax(&g_best_prior[b * OO + lane], cand);
        }
    }

    if (valid) {
        unsigned char fl = (2.f * bI >= bD) ? 0x80 : 0;   // iou >= 0.5
        g_match[(size_t)b * PP + p] = (unsigned char)besto | fl;
    }
}

// ---------------- kernel 2: fused CE / positive losses ----------------
// Per-warp 4-deep cp.async ring, NO block barriers in the mainloop.
// grid: (51, 64), block 256 (8 warps); 408 warps/batch x 40 rows = 16320
__global__ void __launch_bounds__(256)
k_main(const float* __restrict__ arm_loc,
       const float* __restrict__ arm_conf,
       const float* __restrict__ odm_loc,
       const float* __restrict__ odm_conf,
       const float* __restrict__ priors,
       const float* __restrict__ gt_boxes,
       const int*   __restrict__ gt_labels) {
    extern __shared__ float sh[];            // 8 warps * 4 slots * 648 floats = 82944 B
    __shared__ float4 s_gtb[OO];
    __shared__ int    s_lab[OO];
    __shared__ int    s_fp[OO];

    int b = blockIdx.y;
    int tid = threadIdx.x;
    int w = tid >> 5, lane = tid & 31;
    int warpg = blockIdx.x * 8 + w;          // 0..407
    int row0 = warpg * (WCH * WNC);          // first of this warp's 40 rows
    size_t bbase = (size_t)b * PP;
    const float* confb = odm_conf + bbase * CC;
    float* ws = sh + w * (4 * CHF);

    // prologue: issue chunks 0..2 into slots 0..2
    #pragma unroll
    for (int c = 0; c < 3; c++) {
        const float4* src = (const float4*)(confb + (size_t)(row0 + c * WCH) * CC);
        float* dst = ws + c * CHF;
        #pragma unroll
        for (int t = 0; t < 6; t++) {
            int i = lane + t * 32;
            if (i < CHF4) cp16(dst + i * 4, src + i);
        }
        asm volatile("cp.async.commit_group;\n" ::);
    }

    if (tid < OO) {
        unsigned long long fc = g_best_prior[b * OO + tid];
        // hi==0 (incl. first-call zero-init) -> reference forces prior 0
        s_fp[tid] = (fc >> 32) ? (int)(0xFFFFFFFFu - (unsigned)(fc & 0xFFFFFFFFu)) : 0;
        s_gtb[tid] = ((const float4*)gt_boxes)[b * OO + tid];
        s_lab[tid] = gt_labels[b * OO + tid];
    }
    __syncthreads();                          // only block barrier (s_fp/s_lab ready)

    int r = lane >> 2, q = lane & 3;          // 8 rows x 4 lanes per row

    #pragma unroll
    for (int c = 0; c < WNC; c++) {
        if (c + 3 < WNC) {                    // issue ahead into slot (c+3)&3
            const float4* src = (const float4*)(confb + (size_t)(row0 + (c + 3) * WCH) * CC);
            float* dst = ws + ((c + 3) & 3) * CHF;
            #pragma unroll
            for (int t = 0; t < 6; t++) {
                int i = lane + t * 32;
                if (i < CHF4) cp16(dst + i * 4, src + i);
            }
            asm volatile("cp.async.commit_group;\n" ::);
        }
        // wait until chunk c has landed (static counts; loop fully unrolled)
        if (c < 2)       asm volatile("cp.async.wait_group 3;\n" ::);
        else if (c == 2) asm volatile("cp.async.wait_group 2;\n" ::);
        else if (c == 3) asm volatile("cp.async.wait_group 1;\n" ::);
        else             asm volatile("cp.async.wait_group 0;\n" ::);
        __syncwarp();

        const float* s = ws + (c & 3) * CHF;
        int p0 = row0 + c * WCH;
        size_t rowbase = bbase + p0;

        unsigned char m = 0;
        if (q == 0) m = g_match[rowbase + r];  // 8 lanes, 8 consecutive bytes

        // lane (r,q): sum exp over elements [q*20, q*20+20); q==0 adds element 80
        const float* rp = s + r * CC + q * 20;
        float a0 = 0.f, a1 = 0.f;
        #pragma unroll
        for (int j = 0; j < 20; j += 2) {
            a0 += __expf(rp[j]);
            a1 += __expf(rp[j + 1]);
        }
        float e = a0 + a1;
        if (q == 0) e += __expf(s[r * CC + 80]);
        e += __shfl_xor_sync(0xFFFFFFFFu, e, 1);
        e += __shfl_xor_sync(0xFFFFFFFFu, e, 2);

        // forced-positive: lane (r,q) checks objects q*6..q*6+5 for row r; max-o wins
        int prow = p0 + r;
        int fo = -1;
        #pragma unroll
        for (int j = 0; j < 6; j++) {
            int o = q * 6 + j;
            if (s_fp[o] == prow) fo = o;       // ascending o: last write wins
        }
        fo = max(fo, __shfl_xor_sync(0xFFFFFFFFu, fo, 1));
        fo = max(fo, __shfl_xor_sync(0xFFFFFFFFu, fo, 2));

        if (q == 0) {                          // 8 row-leader lanes in parallel
            float lse = __logf(e);
            size_t idx = rowbase + r;
            int obj; bool flag;
            if (fo >= 0) { obj = fo; flag = true; }
            else         { obj = m & 0x1F; flag = (m & 0x80) != 0; }
            int conf_t = flag ? s_lab[obj] : 0;
            float ce = lse - s[r * CC + conf_t];

            float2 ac = ((const float2*)arm_conf)[idx];
            // softmax[1] > 0.01  <=>  (y - x) > log(0.01/0.99)
            bool pos = (conf_t > 0) && ((ac.y - ac.x) > -4.5951199f);

            g_ce_mine[idx] = pos ? 0.f : ce;

            if (pos) {                          // rare (~24/batch)
                int p = p0 + r;
                float4 pr = ((const float4*)priors)[p];
                float4 al = ((const float4*)arm_loc)[idx];
                float cx = pr.x + al.x * 0.1f * pr.z;
                float cy = pr.y + al.y * 0.1f * pr.w;
                float wd = pr.z * __expf(al.z * 0.2f);
                float ht = pr.w * __expf(al.w * 0.2f);
                float x1 = cx - wd * 0.5f, y1 = cy - ht * 0.5f;
                float x2 = cx + wd * 0.5f, y2 = cy + ht * 0.5f;
                float dcx = (x1 + x2) * 0.5f, dcy = (y1 + y2) * 0.5f;
                float dw = x2 - x1, dh = y2 - y1;
                float4 t = s_gtb[obj];
                float gcx = ((t.x + t.z) * 0.5f - dcx) / (0.1f * dw);
                float gcy = ((t.y + t.w) * 0.5f - dcy) / (0.1f * dh);
                float gw  = __logf((t.z - t.x) / dw) / 0.2f;
                float gh  = __logf((t.w - t.y) / dh) / 0.2f;
                float4 ol = ((const float4*)odm_loc)[idx];
                float d0 = fabsf(ol.x - gcx), d1 = fabsf(ol.y - gcy);
                float d2 = fabsf(ol.z - gw),  d3 = fabsf(ol.w - gh);
                float sl = (d0 < 1.f ? 0.5f * d0 * d0 : d0 - 0.5f)
                         + (d1 < 1.f ? 0.5f * d1 * d1 : d1 - 0.5f)
                         + (d2 < 1.f ? 0.5f * d2 * d2 : d2 - 0.5f)
                         + (d3 < 1.f ? 0.5f * d3 * d3 : d3 - 0.5f);
                atomicAdd(&g_loss_l, (double)sl);
                atomicAdd(&g_loss_c, (double)ce);
                atomicAdd(&g_pos_count[b], 1);
            }
        }
        __syncwarp();   // all lanes done reading slot (c&3) before it is refilled
    }
}

// ---------------- kernel 3: per-batch top-k sum, 4-pass radix select ----------------
// grid: 64 blocks, block 1024, dynamic smem = PP*4. Also re-arms g_best_prior.
__global__ void __launch_bounds__(1024) k_topk() {
    int b = blockIdx.x;
    extern __shared__ unsigned sm[];
    __shared__ int s_hist[256];
    __shared__ int s_rem;
    __shared__ unsigned s_pref;
    __shared__ double s_sum;
    __shared__ int s_cgt;
    int t = threadIdx.x;
    int lane = t & 31;

    if (t < OO) g_best_prior[b * OO + t] = 0x00000000FFFFFFFFull;  // next replay

    for (int i = t; i < PP; i += 1024)
        sm[i] = __float_as_uint(g_ce_mine[(size_t)b * PP + i]);
    if (t == 0) { s_sum = 0.0; s_cgt = 0; }
    __syncthreads();

    int np = g_pos_count[b];
    int k = 3 * np; if (k > PP - 1) k = PP - 1;
    if (k <= 0) return;

    int rem = k;
    unsigned pref = 0;
    #pragma unroll
    for (int d = 24; d >= 0; d -= 8) {
        if (t < 256) s_hist[t] = 0;
        __syncthreads();
        unsigned pmask = (d == 24) ? 0u : (0xFFFFFFFFu << (d + 8));
        for (int i = t; i < 16384; i += 1024) {   // uniform trips; collectives converged
            bool part = false; unsigned bin = 0;
            if (i < PP) {
                unsigned v = sm[i];
                part = ((v & pmask) == pref);
                bin = (v >> d) & 0xFFu;
            }
            unsigned act = __ballot_sync(0xFFFFFFFFu, part);
            if (part) {
                unsigned same = __match_any_sync(act, bin);
                if ((__ffs(same) - 1) == lane)
                    atomicAdd(&s_hist[bin], __popc(same));
            }
        }
        __syncthreads();
        if (t < 32) {
            int loc[8]; int s8 = 0;
            #pragma unroll
            for (int j = 0; j < 8; j++) { loc[j] = s_hist[t * 8 + j]; s8 += loc[j]; }
            int suf = s8;
            #pragma unroll
            for (int sh = 1; sh < 32; sh <<= 1) {
                int o = __shfl_down_sync(0xFFFFFFFFu, suf, sh);
                if (t + sh < 32) suf += o;
            }
            int above = suf - s8;
            int cand = -1, candgt = 0;
            int run = above;
            #pragma unroll
            for (int j = 7; j >= 0; j--) {
                int gt = run;
                run += loc[j];
                if (cand < 0 && run >= rem) { cand = t * 8 + j; candgt = gt; }
            }
            int wm = __reduce_max_sync(0xFFFFFFFFu, (unsigned)(cand + 1)) - 1;
            if (cand == wm && cand >= 0) {
                s_rem = rem - candgt;
                s_pref = pref | ((unsigned)cand << d);
            }
        }
        __syncthreads();
        rem = s_rem;
        pref = s_pref;
        __syncthreads();
    }
    unsigned lo = pref;

    double sum = 0.0; int cgt = 0;
    for (int i = t; i < PP; i += 1024) {
        unsigned v = sm[i];
        if (v > lo) { sum += (double)__uint_as_float(v); cgt++; }
    }
    #pragma unroll
    for (int s = 16; s > 0; s >>= 1) {
        sum += __shfl_xor_sync(0xFFFFFFFFu, sum, s);
        cgt += __shfl_xor_sync(0xFFFFFFFFu, cgt, s);
    }
    if (lane == 0) { atomicAdd(&s_sum, sum); atomicAdd(&s_cgt, cgt); }
    __syncthreads();
    if (t == 0) {
        double S = s_sum + (double)(k - s_cgt) * (double)__uint_as_float(lo);
        atomicAdd(&g_loss_c, S);
    }
}

// ---------------- kernel 4: finalize + reset accumulators ----------------
__global__ void k_final(float* __restrict__ out) {
    __shared__ int s[64];
    int t = threadIdx.x;
    s[t] = g_pos_count[t];
    g_pos_count[t] = 0;                       // reset for next replay
    __syncthreads();
    #pragma unroll
    for (int sft = 32; sft > 0; sft >>= 1) {
        if (t < sft) s[t] += s[t + sft];
        __syncthreads();
    }
    if (t == 0) {
        double N = (double)s[0];
        out[0] = (float)(g_loss_l / N);
        out[1] = (float)(g_loss_c / N);
        g_loss_l = 0.0;                       // reset for next replay
        g_loss_c = 0.0;
    }
}

// ---------------- launch ----------------
extern "C" void kernel_launch(void* const* d_in, const int* in_sizes, int n_in,
                              void* d_out, int out_size) {
    const float* arm_loc  = (const float*)d_in[0];
    const float* arm_conf = (const float*)d_in[1];
    const float* odm_loc  = (const float*)d_in[2];
    const float* odm_conf = (const float*)d_in[3];
    const float* priors   = (const float*)d_in[4];
    const float* gt_boxes = (const float*)d_in[5];
    const int*   gt_labels= (const int*)  d_in[6];
    float* out = (float*)d_out;

    int kmain_smem = 8 * 4 * CHF * (int)sizeof(float);   // 82944 B
    cudaFuncSetAttribute(k_main, cudaFuncAttributeMaxDynamicSharedMemorySize,
                         kmain_smem);
    cudaFuncSetAttribute(k_topk, cudaFuncAttributeMaxDynamicSharedMemorySize,
                         PP * (int)sizeof(unsigned));

    {
        dim3 g(128, BB);
        k_match<<<g, 128>>>(arm_loc, priors, gt_boxes);
    }
    {
        dim3 g(51, BB);
        k_main<<<g, 256, kmain_smem>>>(arm_loc, arm_conf, odm_loc, odm_conf,
                                       priors, gt_boxes, gt_labels);
    }
    k_topk<<<BB, 1024, PP * (int)sizeof(unsigned)>>>();
    k_final<<<1, 64>>>(out);
}